// round 3
// baseline (speedup 1.0000x reference)
#include <cuda_runtime.h>

#define B_   2
#define S_   2048
#define D_   1024
#define H_   16
#define DK_  64
#define MTOT (B_ * S_)   // 4096

// Scratch (device globals — no allocation allowed)
__device__ float g_Q[B_ * S_ * D_];
__device__ float g_K[B_ * S_ * D_];
__device__ float g_V[B_ * S_ * D_];
__device__ float g_att[B_ * S_ * D_];

// ---------------------------------------------------------------------------
// 128x128x8 fp32 SGEMM, 256 threads, 8x8 thread tiles.  C[M,N] = A[M,K] @ B[K,N]
// M,N,K all multiples of 128 here (4096/1024/1024).
// ---------------------------------------------------------------------------
__global__ __launch_bounds__(256) void sgemm128(const float* __restrict__ A,
                                                const float* __restrict__ Bm,
                                                float* __restrict__ C,
                                                int M, int N, int K)
{
    __shared__ float As[8 * 128];   // transposed: As[k][m]
    __shared__ float Bs[8 * 128];   // Bs[k][n]

    const int tid = threadIdx.x;
    const int tx  = tid & 15;       // 16 threads along N
    const int ty  = tid >> 4;       // 16 threads along M
    const int bx  = blockIdx.x;     // N tile
    const int by  = blockIdx.y;     // M tile

    const float* Ab = A + (size_t)by * 128 * K;
    const float* Bb = Bm + (size_t)bx * 128;

    float acc[8][8];
#pragma unroll
    for (int i = 0; i < 8; i++)
#pragma unroll
        for (int j = 0; j < 8; j++) acc[i][j] = 0.f;

    const int arow = tid >> 1;          // 0..127
    const int acol = (tid & 1) << 2;    // 0 or 4
    const int brow = tid >> 5;          // 0..7
    const int bcol = (tid & 31) << 2;   // 0..124

    for (int k0 = 0; k0 < K; k0 += 8) {
        float4 a4 = *(const float4*)(Ab + (size_t)arow * K + k0 + acol);
        As[(acol + 0) * 128 + arow] = a4.x;
        As[(acol + 1) * 128 + arow] = a4.y;
        As[(acol + 2) * 128 + arow] = a4.z;
        As[(acol + 3) * 128 + arow] = a4.w;
        *(float4*)&Bs[brow * 128 + bcol] =
            *(const float4*)(Bb + (size_t)(k0 + brow) * N + bcol);
        __syncthreads();

#pragma unroll
        for (int kk = 0; kk < 8; kk++) {
            float4 a0 = *(float4*)&As[kk * 128 + ty * 8];
            float4 a1 = *(float4*)&As[kk * 128 + ty * 8 + 4];
            float4 b0 = *(float4*)&Bs[kk * 128 + tx * 8];
            float4 b1 = *(float4*)&Bs[kk * 128 + tx * 8 + 4];
            float ar[8] = {a0.x, a0.y, a0.z, a0.w, a1.x, a1.y, a1.z, a1.w};
            float br[8] = {b0.x, b0.y, b0.z, b0.w, b1.x, b1.y, b1.z, b1.w};
#pragma unroll
            for (int i = 0; i < 8; i++)
#pragma unroll
                for (int j = 0; j < 8; j++)
                    acc[i][j] += ar[i] * br[j];
        }
        __syncthreads();
    }

#pragma unroll
    for (int i = 0; i < 8; i++) {
        float* crow = C + (size_t)(by * 128 + ty * 8 + i) * N + bx * 128 + tx * 8;
        *(float4*)(crow)     = make_float4(acc[i][0], acc[i][1], acc[i][2], acc[i][3]);
        *(float4*)(crow + 4) = make_float4(acc[i][4], acc[i][5], acc[i][6], acc[i][7]);
    }
}

// ---------------------------------------------------------------------------
// Causal flash attention, fp32. 64 query rows per block, 64-wide KV tiles.
// Q/K/V/O viewed as [B*S, D] with per-head column offset h*64.
// 256 threads as 16x16; each thread owns a 4(query) x 4 register tile.
// Row groups (16 lanes with same ty) live in one half-warp -> shfl reductions.
// ---------------------------------------------------------------------------
__global__ __launch_bounds__(256) void attn64(const float* __restrict__ Q,
                                              const float* __restrict__ K,
                                              const float* __restrict__ V,
                                              float* __restrict__ O)
{
    __shared__ float Qs[64 * 64];     // Qs[q][dk]
    __shared__ float KtPs[64 * 64];   // K^T during scores (Kt[dk][kv]); P[q][kv] during PV
    __shared__ float Vs[64 * 64];     // Vs[kv][dk]

    const int tid = threadIdx.x;
    const int tx  = tid & 15;
    const int ty  = tid >> 4;
    const int qt  = blockIdx.x;       // query tile
    const int bh  = blockIdx.y;       // b*H + h
    const int b   = bh >> 4;
    const int h   = bh & 15;

    const size_t base = (size_t)b * S_ * D_ + (size_t)h * DK_;
    const float* Qb = Q + base;
    const float* Kb = K + base;
    const float* Vb = V + base;
    float*       Ob = O + base;

    const int q0 = qt * 64;

    // Load Q tile (coalesced float4, natural layout)
#pragma unroll
    for (int l = 0; l < 4; l++) {
        int idx = tid + l * 256;
        int r   = idx >> 4;
        int d4  = (idx & 15) << 2;
        *(float4*)&Qs[r * 64 + d4] =
            *(const float4*)(Qb + (size_t)(q0 + r) * D_ + d4);
    }

    float m[4], lsum[4], o[4][4];
#pragma unroll
    for (int i = 0; i < 4; i++) {
        m[i] = -1e30f; lsum[i] = 0.f;
#pragma unroll
        for (int j = 0; j < 4; j++) o[i][j] = 0.f;
    }

    const float inv_scale = 0.125f;   // 1/sqrt(DK)

    for (int kvt = 0; kvt <= qt; kvt++) {
        const int kv0 = kvt * 64;
        __syncthreads();  // previous PV done before overwriting Kt/Vs
#pragma unroll
        for (int l = 0; l < 4; l++) {
            int idx = tid + l * 256;
            int c   = idx >> 4;
            int d4  = (idx & 15) << 2;
            float4 k4 = *(const float4*)(Kb + (size_t)(kv0 + c) * D_ + d4);
            KtPs[(d4 + 0) * 64 + c] = k4.x;   // transpose for conflict-free score reads
            KtPs[(d4 + 1) * 64 + c] = k4.y;
            KtPs[(d4 + 2) * 64 + c] = k4.z;
            KtPs[(d4 + 3) * 64 + c] = k4.w;
            *(float4*)&Vs[c * 64 + d4] =
                *(const float4*)(Vb + (size_t)(kv0 + c) * D_ + d4);
        }
        __syncthreads();

        // Scores S = Q @ K^T  (4x4 per thread)
        float s[4][4];
#pragma unroll
        for (int i = 0; i < 4; i++)
#pragma unroll
            for (int j = 0; j < 4; j++) s[i][j] = 0.f;

#pragma unroll 8
        for (int kk = 0; kk < 64; kk++) {
            float4 kq = *(float4*)&KtPs[kk * 64 + tx * 4];  // conflict-free (float4 phases)
            float a0 = Qs[(ty * 4 + 0) * 64 + kk];          // broadcast within half-warp
            float a1 = Qs[(ty * 4 + 1) * 64 + kk];
            float a2 = Qs[(ty * 4 + 2) * 64 + kk];
            float a3 = Qs[(ty * 4 + 3) * 64 + kk];
            s[0][0] += a0 * kq.x; s[0][1] += a0 * kq.y; s[0][2] += a0 * kq.z; s[0][3] += a0 * kq.w;
            s[1][0] += a1 * kq.x; s[1][1] += a1 * kq.y; s[1][2] += a1 * kq.z; s[1][3] += a1 * kq.w;
            s[2][0] += a2 * kq.x; s[2][1] += a2 * kq.y; s[2][2] += a2 * kq.z; s[2][3] += a2 * kq.w;
            s[3][0] += a3 * kq.x; s[3][1] += a3 * kq.y; s[3][2] += a3 * kq.z; s[3][3] += a3 * kq.w;
        }

        // Online softmax update (scores already need /SCALE)
        const bool diag = (kvt == qt);
#pragma unroll
        for (int i = 0; i < 4; i++) {
            const int qg = q0 + ty * 4 + i;
            float rmax = -1e30f;
#pragma unroll
            for (int j = 0; j < 4; j++) {
                float sv = s[i][j] * inv_scale;
                if (diag && (kv0 + tx * 4 + j > qg)) sv = -1e30f;
                s[i][j] = sv;
                rmax = fmaxf(rmax, sv);
            }
#pragma unroll
            for (int off = 8; off > 0; off >>= 1)
                rmax = fmaxf(rmax, __shfl_xor_sync(0xffffffffu, rmax, off, 16));
            float mnew = fmaxf(m[i], rmax);
            float corr = __expf(m[i] - mnew);
            m[i] = mnew;
            float psum = 0.f;
#pragma unroll
            for (int j = 0; j < 4; j++) {
                float p = __expf(s[i][j] - mnew);   // masked -> exp(-1e30) == 0
                s[i][j] = p;
                psum += p;
            }
#pragma unroll
            for (int off = 8; off > 0; off >>= 1)
                psum += __shfl_xor_sync(0xffffffffu, psum, off, 16);
            lsum[i] = lsum[i] * corr + psum;
#pragma unroll
            for (int j = 0; j < 4; j++) o[i][j] *= corr;
        }

        __syncthreads();  // everyone done reading Kt before P overwrites the buffer
#pragma unroll
        for (int i = 0; i < 4; i++)
            *(float4*)&KtPs[(ty * 4 + i) * 64 + tx * 4] =
                make_float4(s[i][0], s[i][1], s[i][2], s[i][3]);
        __syncthreads();

        // O += P @ V
#pragma unroll 8
        for (int cc = 0; cc < 64; cc++) {
            float4 v4 = *(float4*)&Vs[cc * 64 + tx * 4];
            float p0 = KtPs[(ty * 4 + 0) * 64 + cc];
            float p1 = KtPs[(ty * 4 + 1) * 64 + cc];
            float p2 = KtPs[(ty * 4 + 2) * 64 + cc];
            float p3 = KtPs[(ty * 4 + 3) * 64 + cc];
            o[0][0] += p0 * v4.x; o[0][1] += p0 * v4.y; o[0][2] += p0 * v4.z; o[0][3] += p0 * v4.w;
            o[1][0] += p1 * v4.x; o[1][1] += p1 * v4.y; o[1][2] += p1 * v4.z; o[1][3] += p1 * v4.w;
            o[2][0] += p2 * v4.x; o[2][1] += p2 * v4.y; o[2][2] += p2 * v4.z; o[2][3] += p2 * v4.w;
            o[3][0] += p3 * v4.x; o[3][1] += p3 * v4.y; o[3][2] += p3 * v4.z; o[3][3] += p3 * v4.w;
        }
    }

    // Normalize and write [B*S, D] with head column offset
#pragma unroll
    for (int i = 0; i < 4; i++) {
        float invl = 1.0f / lsum[i];
        float4 r = make_float4(o[i][0] * invl, o[i][1] * invl,
                               o[i][2] * invl, o[i][3] * invl);
        *(float4*)(Ob + (size_t)(q0 + ty * 4 + i) * D_ + tx * 4) = r;
    }
}

// ---------------------------------------------------------------------------
extern "C" void kernel_launch(void* const* d_in, const int* in_sizes, int n_in,
                              void* d_out, int out_size)
{
    (void)in_sizes; (void)n_in; (void)out_size;
    const float* x  = (const float*)d_in[0];
    const float* Wq = (const float*)d_in[1];
    const float* Wk = (const float*)d_in[2];
    const float* Wv = (const float*)d_in[3];
    const float* Wo = (const float*)d_in[4];
    float* out = (float*)d_out;

    float *qp, *kp, *vp, *ap;
    cudaGetSymbolAddress((void**)&qp, g_Q);
    cudaGetSymbolAddress((void**)&kp, g_K);
    cudaGetSymbolAddress((void**)&vp, g_V);
    cudaGetSymbolAddress((void**)&ap, g_att);

    dim3 gg(D_ / 128, MTOT / 128);   // (8, 32)

    sgemm128<<<gg, 256>>>(x, Wq, qp, MTOT, D_, D_);
    sgemm128<<<gg, 256>>>(x, Wk, kp, MTOT, D_, D_);
    sgemm128<<<gg, 256>>>(x, Wv, vp, MTOT, D_, D_);

    attn64<<<dim3(S_ / 64, B_ * H_), 256>>>(qp, kp, vp, ap);

    sgemm128<<<gg, 256>>>(ap, Wo, out, MTOT, D_, D_);
}

// round 5
// speedup vs baseline: 1.7104x; 1.7104x over previous
#include <cuda_runtime.h>
#include <cstdint>

#define B_   2
#define S_   2048
#define D_   1024
#define H_   16
#define DK_  64
#define MTOT (B_ * S_)   // 4096

// ---------------------------------------------------------------------------
// Scratch (device globals — no allocation allowed)
// ---------------------------------------------------------------------------
__device__ float g_Q[MTOT * D_];
__device__ float g_K[MTOT * D_];
__device__ float g_V[MTOT * D_];
__device__ float g_att[MTOT * D_];

// ---------------------------------------------------------------------------
// Helpers (baseline PTX only — no sm_103a-feature instructions)
// ---------------------------------------------------------------------------
__device__ __forceinline__ uint32_t smem_u32(const void* p) {
    uint32_t a;
    asm("{ .reg .u64 t; cvta.to.shared.u64 t, %1; cvt.u32.u64 %0, t; }"
        : "=r"(a) : "l"(p));
    return a;
}
__device__ __forceinline__ void cp16(uint32_t s, const void* g) {
    asm volatile("cp.async.cg.shared.global [%0], [%1], 16;"
                 :: "r"(s), "l"(g) : "memory");
}
#define CP_COMMIT() asm volatile("cp.async.commit_group;" ::: "memory")
#define CP_WAIT(n)  asm volatile("cp.async.wait_group %0;" :: "n"(n) : "memory")

__device__ __forceinline__ uint32_t f2tf(float f) {
    uint32_t u;
    asm("cvt.rna.tf32.f32 %0, %1;" : "=r"(u) : "f"(f));
    return u;
}
__device__ __forceinline__ void mma_tf32(float* c, const uint32_t* a,
                                         uint32_t b0, uint32_t b1) {
    asm volatile(
        "mma.sync.aligned.m16n8k8.row.col.f32.tf32.tf32.f32 "
        "{%0,%1,%2,%3}, {%4,%5,%6,%7}, {%8,%9}, {%0,%1,%2,%3};"
        : "+f"(c[0]), "+f"(c[1]), "+f"(c[2]), "+f"(c[3])
        : "r"(a[0]), "r"(a[1]), "r"(a[2]), "r"(a[3]), "r"(b0), "r"(b1));
}

// ---------------------------------------------------------------------------
// TF32 tensor-core GEMM: C[M,N] = A[M,K] @ W[K,N]   (fp32 in / fp32 out)
// 128x128 CTA tile, 8 warps in 2x4 (warp tile 64x32), K-chunks of 32,
// cp.async double buffering. Fragments hand-loaded from padded smem:
//   A stored [m][k] pitch 36  -> frag banks (4m'+k') unique, conflict-free
//   B stored [k][n] pitch 136 -> frag banks (8k'+n') unique, conflict-free
// ---------------------------------------------------------------------------
#define KCH     32
#define APITCH  36
#define BPITCH  136
#define AFLOATS (128 * APITCH)          // 4608
#define BFLOATS (KCH * BPITCH)          // 4352
#define ABYTES  (AFLOATS * 4)
#define BBYTES  (BFLOATS * 4)
#define GSMEM   (2 * (ABYTES + BBYTES)) // 71680 B

__global__ __launch_bounds__(256) void gemm_tf32(const float* __restrict__ A,
                                                 const float* __restrict__ W,
                                                 float* __restrict__ C,
                                                 int M, int N, int K)
{
    extern __shared__ float sm[];
    const int tid  = threadIdx.x;
    const int wid  = tid >> 5;
    const int lane = tid & 31;
    const int g    = lane >> 2;     // group id (0..7)
    const int tig  = lane & 3;      // thread-in-group (0..3)
    const int bx   = blockIdx.x, by = blockIdx.y;
    const int m0w  = (wid >> 2) * 64;
    const int n0w  = (wid & 3) * 32;

    const float* Ab = A + (size_t)by * 128 * K;
    const float* Wb = W + bx * 128;
    const uint32_t sbase = smem_u32(sm);

    float acc[4][4][4];
#pragma unroll
    for (int i = 0; i < 4; i++)
#pragma unroll
        for (int j = 0; j < 4; j++)
#pragma unroll
            for (int q = 0; q < 4; q++) acc[i][j][q] = 0.f;

    const int NC = K / KCH;   // 32

    // --- async copy of one K-chunk into buffer `buf` -----------------------
    auto copy_chunk = [&](int c, int buf) {
        const float* Ac = Ab + c * KCH;
        const float* Bc = Wb + (size_t)c * KCH * N;
        uint32_t ab = sbase + (uint32_t)buf * ABYTES;
        uint32_t bb = sbase + 2u * ABYTES + (uint32_t)buf * BBYTES;
#pragma unroll
        for (int p = 0; p < 4; p++) {
            int idx = tid + p * 256;
            int r  = idx >> 3, kq = (idx & 7) << 2;           // A: 128r x 32k
            cp16(ab + (uint32_t)(r * APITCH + kq) * 4, Ac + (size_t)r * K + kq);
            int kb = idx >> 5, nq = (idx & 31) << 2;          // B: 32k x 128n
            cp16(bb + (uint32_t)(kb * BPITCH + nq) * 4, Bc + (size_t)kb * N + nq);
        }
        CP_COMMIT();
    };

    copy_chunk(0, 0);

    for (int c = 0; c < NC; c++) {
        const int buf = c & 1;
        if (c + 1 < NC) { copy_chunk(c + 1, buf ^ 1); CP_WAIT(1); }
        else            { CP_WAIT(0); }
        __syncthreads();

        const float* As = sm + buf * AFLOATS;
        const float* Bs = sm + 2 * AFLOATS + buf * BFLOATS;

#pragma unroll
        for (int kk = 0; kk < KCH; kk += 8) {
            uint32_t a[4][4];
#pragma unroll
            for (int i = 0; i < 4; i++) {
                int r = m0w + 16 * i + g;
                a[i][0] = f2tf(As[r * APITCH + kk + tig]);
                a[i][1] = f2tf(As[(r + 8) * APITCH + kk + tig]);
                a[i][2] = f2tf(As[r * APITCH + kk + tig + 4]);
                a[i][3] = f2tf(As[(r + 8) * APITCH + kk + tig + 4]);
            }
#pragma unroll
            for (int j = 0; j < 4; j++) {
                uint32_t b0 = f2tf(Bs[(kk + tig) * BPITCH + n0w + 8 * j + g]);
                uint32_t b1 = f2tf(Bs[(kk + tig + 4) * BPITCH + n0w + 8 * j + g]);
#pragma unroll
                for (int i = 0; i < 4; i++)
                    mma_tf32(acc[i][j], a[i], b0, b1);
            }
        }
        __syncthreads();   // all warps done with buf before chunk c+2 overwrites
    }

    // --- epilogue: direct fp32 stores (float2 per fragment half) -----------
#pragma unroll
    for (int i = 0; i < 4; i++) {
        int r0 = by * 128 + m0w + 16 * i + g;
#pragma unroll
        for (int j = 0; j < 4; j++) {
            int cc = bx * 128 + n0w + 8 * j + 2 * tig;
            *(float2*)&C[(size_t)r0 * N + cc] =
                make_float2(acc[i][j][0], acc[i][j][1]);
            *(float2*)&C[(size_t)(r0 + 8) * N + cc] =
                make_float2(acc[i][j][2], acc[i][j][3]);
        }
    }
}

// ---------------------------------------------------------------------------
// Causal flash attention, fp32 (unchanged — next round's target)
// ---------------------------------------------------------------------------
__global__ __launch_bounds__(256) void attn64(const float* __restrict__ Q,
                                              const float* __restrict__ K,
                                              const float* __restrict__ V,
                                              float* __restrict__ O)
{
    __shared__ float Qs[64 * 64];
    __shared__ float KtPs[64 * 64];
    __shared__ float Vs[64 * 64];

    const int tid = threadIdx.x;
    const int tx  = tid & 15;
    const int ty  = tid >> 4;
    const int qt  = blockIdx.x;
    const int bh  = blockIdx.y;
    const int b   = bh >> 4;
    const int h   = bh & 15;

    const size_t base = (size_t)b * S_ * D_ + (size_t)h * DK_;
    const float* Qb = Q + base;
    const float* Kb = K + base;
    const float* Vb = V + base;
    float*       Ob = O + base;

    const int q0 = qt * 64;

#pragma unroll
    for (int l = 0; l < 4; l++) {
        int idx = tid + l * 256;
        int r   = idx >> 4;
        int d4  = (idx & 15) << 2;
        *(float4*)&Qs[r * 64 + d4] =
            *(const float4*)(Qb + (size_t)(q0 + r) * D_ + d4);
    }

    float m[4], lsum[4], o[4][4];
#pragma unroll
    for (int i = 0; i < 4; i++) {
        m[i] = -1e30f; lsum[i] = 0.f;
#pragma unroll
        for (int j = 0; j < 4; j++) o[i][j] = 0.f;
    }

    const float inv_scale = 0.125f;

    for (int kvt = 0; kvt <= qt; kvt++) {
        const int kv0 = kvt * 64;
        __syncthreads();
#pragma unroll
        for (int l = 0; l < 4; l++) {
            int idx = tid + l * 256;
            int c   = idx >> 4;
            int d4  = (idx & 15) << 2;
            float4 k4 = *(const float4*)(Kb + (size_t)(kv0 + c) * D_ + d4);
            KtPs[(d4 + 0) * 64 + c] = k4.x;
            KtPs[(d4 + 1) * 64 + c] = k4.y;
            KtPs[(d4 + 2) * 64 + c] = k4.z;
            KtPs[(d4 + 3) * 64 + c] = k4.w;
            *(float4*)&Vs[c * 64 + d4] =
                *(const float4*)(Vb + (size_t)(kv0 + c) * D_ + d4);
        }
        __syncthreads();

        float s[4][4];
#pragma unroll
        for (int i = 0; i < 4; i++)
#pragma unroll
            for (int j = 0; j < 4; j++) s[i][j] = 0.f;

#pragma unroll 8
        for (int kk = 0; kk < 64; kk++) {
            float4 kq = *(float4*)&KtPs[kk * 64 + tx * 4];
            float a0 = Qs[(ty * 4 + 0) * 64 + kk];
            float a1 = Qs[(ty * 4 + 1) * 64 + kk];
            float a2 = Qs[(ty * 4 + 2) * 64 + kk];
            float a3 = Qs[(ty * 4 + 3) * 64 + kk];
            s[0][0] += a0 * kq.x; s[0][1] += a0 * kq.y; s[0][2] += a0 * kq.z; s[0][3] += a0 * kq.w;
            s[1][0] += a1 * kq.x; s[1][1] += a1 * kq.y; s[1][2] += a1 * kq.z; s[1][3] += a1 * kq.w;
            s[2][0] += a2 * kq.x; s[2][1] += a2 * kq.y; s[2][2] += a2 * kq.z; s[2][3] += a2 * kq.w;
            s[3][0] += a3 * kq.x; s[3][1] += a3 * kq.y; s[3][2] += a3 * kq.z; s[3][3] += a3 * kq.w;
        }

        const bool diag = (kvt == qt);
#pragma unroll
        for (int i = 0; i < 4; i++) {
            const int qg = q0 + ty * 4 + i;
            float rmax = -1e30f;
#pragma unroll
            for (int j = 0; j < 4; j++) {
                float sv = s[i][j] * inv_scale;
                if (diag && (kv0 + tx * 4 + j > qg)) sv = -1e30f;
                s[i][j] = sv;
                rmax = fmaxf(rmax, sv);
            }
#pragma unroll
            for (int off = 8; off > 0; off >>= 1)
                rmax = fmaxf(rmax, __shfl_xor_sync(0xffffffffu, rmax, off, 16));
            float mnew = fmaxf(m[i], rmax);
            float corr = __expf(m[i] - mnew);
            m[i] = mnew;
            float psum = 0.f;
#pragma unroll
            for (int j = 0; j < 4; j++) {
                float p = __expf(s[i][j] - mnew);
                s[i][j] = p;
                psum += p;
            }
#pragma unroll
            for (int off = 8; off > 0; off >>= 1)
                psum += __shfl_xor_sync(0xffffffffu, psum, off, 16);
            lsum[i] = lsum[i] * corr + psum;
#pragma unroll
            for (int j = 0; j < 4; j++) o[i][j] *= corr;
        }

        __syncthreads();
#pragma unroll
        for (int i = 0; i < 4; i++)
            *(float4*)&KtPs[(ty * 4 + i) * 64 + tx * 4] =
                make_float4(s[i][0], s[i][1], s[i][2], s[i][3]);
        __syncthreads();

#pragma unroll 8
        for (int cc = 0; cc < 64; cc++) {
            float4 v4 = *(float4*)&Vs[cc * 64 + tx * 4];
            float p0 = KtPs[(ty * 4 + 0) * 64 + cc];
            float p1 = KtPs[(ty * 4 + 1) * 64 + cc];
            float p2 = KtPs[(ty * 4 + 2) * 64 + cc];
            float p3 = KtPs[(ty * 4 + 3) * 64 + cc];
            o[0][0] += p0 * v4.x; o[0][1] += p0 * v4.y; o[0][2] += p0 * v4.z; o[0][3] += p0 * v4.w;
            o[1][0] += p1 * v4.x; o[1][1] += p1 * v4.y; o[1][2] += p1 * v4.z; o[1][3] += p1 * v4.w;
            o[2][0] += p2 * v4.x; o[2][1] += p2 * v4.y; o[2][2] += p2 * v4.z; o[2][3] += p2 * v4.w;
            o[3][0] += p3 * v4.x; o[3][1] += p3 * v4.y; o[3][2] += p3 * v4.z; o[3][3] += p3 * v4.w;
        }
    }

#pragma unroll
    for (int i = 0; i < 4; i++) {
        float invl = 1.0f / lsum[i];
        float4 r = make_float4(o[i][0] * invl, o[i][1] * invl,
                               o[i][2] * invl, o[i][3] * invl);
        *(float4*)(Ob + (size_t)(q0 + ty * 4 + i) * D_ + tx * 4) = r;
    }
}

// ---------------------------------------------------------------------------
extern "C" void kernel_launch(void* const* d_in, const int* in_sizes, int n_in,
                              void* d_out, int out_size)
{
    (void)in_sizes; (void)n_in; (void)out_size;
    const float* x  = (const float*)d_in[0];
    const float* Wq = (const float*)d_in[1];
    const float* Wk = (const float*)d_in[2];
    const float* Wv = (const float*)d_in[3];
    const float* Wo = (const float*)d_in[4];
    float* out = (float*)d_out;

    float *qp, *kp, *vp, *ap;
    cudaGetSymbolAddress((void**)&qp, g_Q);
    cudaGetSymbolAddress((void**)&kp, g_K);
    cudaGetSymbolAddress((void**)&vp, g_V);
    cudaGetSymbolAddress((void**)&ap, g_att);

    cudaFuncSetAttribute(gemm_tf32, cudaFuncAttributeMaxDynamicSharedMemorySize, GSMEM);

    dim3 gg(D_ / 128, MTOT / 128);   // (8, 32)
    gemm_tf32<<<gg, 256, GSMEM>>>(x, Wq, qp, MTOT, D_, D_);
    gemm_tf32<<<gg, 256, GSMEM>>>(x, Wk, kp, MTOT, D_, D_);
    gemm_tf32<<<gg, 256, GSMEM>>>(x, Wv, vp, MTOT, D_, D_);

    attn64<<<dim3(S_ / 64, B_ * H_), 256>>>(qp, kp, vp, ap);

    gemm_tf32<<<gg, 256, GSMEM>>>(ap, Wo, out, MTOT, D_, D_);
}

// round 6
// speedup vs baseline: 3.1989x; 1.8703x over previous
#include <cuda_runtime.h>
#include <cstdint>

#define B_   2
#define S_   2048
#define D_   1024
#define H_   16
#define DK_  64
#define MTOT (B_ * S_)   // 4096

// ---------------------------------------------------------------------------
// Scratch (device globals — no allocation allowed)
// ---------------------------------------------------------------------------
__device__ float g_Q[MTOT * D_];
__device__ float g_K[MTOT * D_];
__device__ float g_V[MTOT * D_];
__device__ float g_att[MTOT * D_];

// ---------------------------------------------------------------------------
// Helpers (baseline PTX only — no sm_103a-feature instructions)
// ---------------------------------------------------------------------------
__device__ __forceinline__ uint32_t smem_u32(const void* p) {
    uint32_t a;
    asm("{ .reg .u64 t; cvta.to.shared.u64 t, %1; cvt.u32.u64 %0, t; }"
        : "=r"(a) : "l"(p));
    return a;
}
__device__ __forceinline__ void cp16(uint32_t s, const void* g) {
    asm volatile("cp.async.cg.shared.global [%0], [%1], 16;"
                 :: "r"(s), "l"(g) : "memory");
}
#define CP_COMMIT() asm volatile("cp.async.commit_group;" ::: "memory")
#define CP_WAIT(n)  asm volatile("cp.async.wait_group %0;" :: "n"(n) : "memory")

__device__ __forceinline__ uint32_t f2tf(float f) {
    uint32_t u;
    asm("cvt.rna.tf32.f32 %0, %1;" : "=r"(u) : "f"(f));
    return u;
}
__device__ __forceinline__ void mma_tf32(float* c, const uint32_t* a,
                                         uint32_t b0, uint32_t b1) {
    asm volatile(
        "mma.sync.aligned.m16n8k8.row.col.f32.tf32.tf32.f32 "
        "{%0,%1,%2,%3}, {%4,%5,%6,%7}, {%8,%9}, {%0,%1,%2,%3};"
        : "+f"(c[0]), "+f"(c[1]), "+f"(c[2]), "+f"(c[3])
        : "r"(a[0]), "r"(a[1]), "r"(a[2]), "r"(a[3]), "r"(b0), "r"(b1));
}

// ---------------------------------------------------------------------------
// TF32 tensor-core GEMM (unchanged from R4): C[M,N] = A[M,K] @ W[K,N]
// ---------------------------------------------------------------------------
#define KCH     32
#define APITCH  36
#define BPITCH  136
#define AFLOATS (128 * APITCH)
#define BFLOATS (KCH * BPITCH)
#define ABYTES  (AFLOATS * 4)
#define BBYTES  (BFLOATS * 4)
#define GSMEM   (2 * (ABYTES + BBYTES)) // 71680 B

__global__ __launch_bounds__(256) void gemm_tf32(const float* __restrict__ A,
                                                 const float* __restrict__ W,
                                                 float* __restrict__ C,
                                                 int M, int N, int K)
{
    extern __shared__ float sm[];
    const int tid  = threadIdx.x;
    const int wid  = tid >> 5;
    const int lane = tid & 31;
    const int g    = lane >> 2;
    const int tig  = lane & 3;
    const int bx   = blockIdx.x, by = blockIdx.y;
    const int m0w  = (wid >> 2) * 64;
    const int n0w  = (wid & 3) * 32;

    const float* Ab = A + (size_t)by * 128 * K;
    const float* Wb = W + bx * 128;
    const uint32_t sbase = smem_u32(sm);

    float acc[4][4][4];
#pragma unroll
    for (int i = 0; i < 4; i++)
#pragma unroll
        for (int j = 0; j < 4; j++)
#pragma unroll
            for (int q = 0; q < 4; q++) acc[i][j][q] = 0.f;

    const int NC = K / KCH;

    auto copy_chunk = [&](int c, int buf) {
        const float* Ac = Ab + c * KCH;
        const float* Bc = Wb + (size_t)c * KCH * N;
        uint32_t ab = sbase + (uint32_t)buf * ABYTES;
        uint32_t bb = sbase + 2u * ABYTES + (uint32_t)buf * BBYTES;
#pragma unroll
        for (int p = 0; p < 4; p++) {
            int idx = tid + p * 256;
            int r  = idx >> 3, kq = (idx & 7) << 2;
            cp16(ab + (uint32_t)(r * APITCH + kq) * 4, Ac + (size_t)r * K + kq);
            int kb = idx >> 5, nq = (idx & 31) << 2;
            cp16(bb + (uint32_t)(kb * BPITCH + nq) * 4, Bc + (size_t)kb * N + nq);
        }
        CP_COMMIT();
    };

    copy_chunk(0, 0);

    for (int c = 0; c < NC; c++) {
        const int buf = c & 1;
        if (c + 1 < NC) { copy_chunk(c + 1, buf ^ 1); CP_WAIT(1); }
        else            { CP_WAIT(0); }
        __syncthreads();

        const float* As = sm + buf * AFLOATS;
        const float* Bs = sm + 2 * AFLOATS + buf * BFLOATS;

#pragma unroll
        for (int kk = 0; kk < KCH; kk += 8) {
            uint32_t a[4][4];
#pragma unroll
            for (int i = 0; i < 4; i++) {
                int r = m0w + 16 * i + g;
                a[i][0] = f2tf(As[r * APITCH + kk + tig]);
                a[i][1] = f2tf(As[(r + 8) * APITCH + kk + tig]);
                a[i][2] = f2tf(As[r * APITCH + kk + tig + 4]);
                a[i][3] = f2tf(As[(r + 8) * APITCH + kk + tig + 4]);
            }
#pragma unroll
            for (int j = 0; j < 4; j++) {
                uint32_t b0 = f2tf(Bs[(kk + tig) * BPITCH + n0w + 8 * j + g]);
                uint32_t b1 = f2tf(Bs[(kk + tig + 4) * BPITCH + n0w + 8 * j + g]);
#pragma unroll
                for (int i = 0; i < 4; i++)
                    mma_tf32(acc[i][j], a[i], b0, b1);
            }
        }
        __syncthreads();
    }

#pragma unroll
    for (int i = 0; i < 4; i++) {
        int r0 = by * 128 + m0w + 16 * i + g;
#pragma unroll
        for (int j = 0; j < 4; j++) {
            int cc = bx * 128 + n0w + 8 * j + 2 * tig;
            *(float2*)&C[(size_t)r0 * N + cc] =
                make_float2(acc[i][j][0], acc[i][j][1]);
            *(float2*)&C[(size_t)(r0 + 8) * N + cc] =
                make_float2(acc[i][j][2], acc[i][j][3]);
        }
    }
}

// ---------------------------------------------------------------------------
// TF32 tensor-core causal flash attention.
// CTA: 128 queries x one (b,h). 8 warps x 16 query rows. KV tiles of 64 keys,
// cp.async double-buffered. Q fragments preloaded to registers (scaled by
// 1/8 before tf32 cvt). Scores in mma accumulators; online softmax on regs
// (shfl over 4-lane row groups). P reuses the Q smem region (warp-private
// rows -> only __syncwarp between STS and LDS). PV via mma with V fragments.
//
// smem (floats): QP 128x68 = 8704 | K 2x(64x68) = 8704 | V 2x(64x72) = 9216
// pitches chosen conflict-free: K/P-A frag banks 4g+tig, V frag banks 8tig+g.
// ---------------------------------------------------------------------------
#define QPITCH  68
#define VPITCH  72
#define OFF_K   8704
#define OFF_V   (8704 + 2 * 4352)
#define KBUF    4352                  // 64*68 floats
#define VBUF    4608                  // 64*72 floats
#define ASMEM   ((OFF_V + 2 * VBUF) * 4)   // 106496 B

__global__ __launch_bounds__(256) void attn_tc(const float* __restrict__ Q,
                                               const float* __restrict__ K,
                                               const float* __restrict__ V,
                                               float* __restrict__ O)
{
    extern __shared__ float sm[];
    float* QP = sm;                 // Q tile, later P tile
    float* Ks = sm + OFF_K;
    float* Vs = sm + OFF_V;

    const int tid  = threadIdx.x;
    const int wid  = tid >> 5;
    const int lane = tid & 31;
    const int g    = lane >> 2;
    const int tig  = lane & 3;

    const int qt = (int)gridDim.x - 1 - (int)blockIdx.x;   // heavy-first
    const int bh = blockIdx.y;
    const int b  = bh >> 4;
    const int h  = bh & 15;

    const size_t base = (size_t)b * S_ * D_ + (size_t)h * DK_;
    const float* Qb = Q + base;
    const float* Kb = K + base;
    const float* Vb = V + base;
    float*       Ob = O + base;

    const int q0  = qt * 128;
    const int r0p = wid * 16 + g;           // this thread's first row in tile
    const uint32_t sb = smem_u32(sm);

    // ---- load Q tile (group 1) ----
#pragma unroll
    for (int p = 0; p < 8; p++) {
        int idx = tid + p * 256;
        int r = idx >> 4, c = (idx & 15) << 2;
        cp16(sb + (uint32_t)(r * QPITCH + c) * 4,
             Qb + (size_t)(q0 + r) * D_ + c);
    }
    CP_COMMIT();

    auto copy_kv = [&](int t, int buf) {
        const float* Kc = Kb + (size_t)(t * 64) * D_;
        const float* Vc = Vb + (size_t)(t * 64) * D_;
#pragma unroll
        for (int p = 0; p < 4; p++) {
            int idx = tid + p * 256;
            int r = idx >> 4, c = (idx & 15) << 2;
            cp16(sb + (uint32_t)(OFF_K + buf * KBUF + r * QPITCH + c) * 4,
                 Kc + (size_t)r * D_ + c);
            cp16(sb + (uint32_t)(OFF_V + buf * VBUF + r * VPITCH + c) * 4,
                 Vc + (size_t)r * D_ + c);
        }
        CP_COMMIT();
    };

    copy_kv(0, 0);      // group 2

    CP_WAIT(1);         // Q ready (kv0 may be in flight)
    __syncthreads();

    // ---- preload Q fragments (scaled by 1/sqrt(DK) = 1/8, exact) ----
    uint32_t qf[8][4];
#pragma unroll
    for (int kt = 0; kt < 8; kt++) {
        int kk = kt * 8;
        qf[kt][0] = f2tf(QP[r0p * QPITCH + kk + tig] * 0.125f);
        qf[kt][1] = f2tf(QP[(r0p + 8) * QPITCH + kk + tig] * 0.125f);
        qf[kt][2] = f2tf(QP[r0p * QPITCH + kk + tig + 4] * 0.125f);
        qf[kt][3] = f2tf(QP[(r0p + 8) * QPITCH + kk + tig + 4] * 0.125f);
    }
    __syncthreads();    // all warps read Q before P overwrites the region

    float m0 = -1e30f, m1 = -1e30f, l0 = 0.f, l1 = 0.f;
    float o[8][4];
#pragma unroll
    for (int nt = 0; nt < 8; nt++)
#pragma unroll
        for (int c = 0; c < 4; c++) o[nt][c] = 0.f;

    const int qrow0 = q0 + r0p;
    const int qrow1 = qrow0 + 8;
    const int ntiles = 2 * qt + 2;

    for (int t = 0; t < ntiles; t++) {
        const int buf = t & 1;
        CP_WAIT(0);
        __syncthreads();            // tile t ready; all warps done with t-1
        if (t + 1 < ntiles) copy_kv(t + 1, buf ^ 1);

        const int kofs = buf * KBUF;
        const int vofs = buf * VBUF;
        const int kv0  = t * 64;

        // ---- scores S = Q @ K^T (accumulators hold 16x64 per warp) ----
        float sacc[8][4];
#pragma unroll
        for (int nt = 0; nt < 8; nt++)
#pragma unroll
            for (int c = 0; c < 4; c++) sacc[nt][c] = 0.f;

#pragma unroll
        for (int kt = 0; kt < 8; kt++) {
#pragma unroll
            for (int nt = 0; nt < 8; nt++) {
                const float* kb = &Ks[kofs + (nt * 8 + g) * QPITCH + kt * 8 + tig];
                uint32_t b0 = f2tf(kb[0]);
                uint32_t b1 = f2tf(kb[4]);
                mma_tf32(sacc[nt], qf[kt], b0, b1);
            }
        }

        // ---- causal mask (only last two tiles intersect the diagonal) ----
        if (kv0 + 63 > q0) {
#pragma unroll
            for (int nt = 0; nt < 8; nt++) {
                int c0 = kv0 + nt * 8 + 2 * tig;
                if (c0     > qrow0) sacc[nt][0] = -1e30f;
                if (c0 + 1 > qrow0) sacc[nt][1] = -1e30f;
                if (c0     > qrow1) sacc[nt][2] = -1e30f;
                if (c0 + 1 > qrow1) sacc[nt][3] = -1e30f;
            }
        }

        // ---- online softmax (rows live on 4-lane groups) ----
        float rmax0 = -1e30f, rmax1 = -1e30f;
#pragma unroll
        for (int nt = 0; nt < 8; nt++) {
            rmax0 = fmaxf(rmax0, fmaxf(sacc[nt][0], sacc[nt][1]));
            rmax1 = fmaxf(rmax1, fmaxf(sacc[nt][2], sacc[nt][3]));
        }
        rmax0 = fmaxf(rmax0, __shfl_xor_sync(0xffffffffu, rmax0, 1));
        rmax0 = fmaxf(rmax0, __shfl_xor_sync(0xffffffffu, rmax0, 2));
        rmax1 = fmaxf(rmax1, __shfl_xor_sync(0xffffffffu, rmax1, 1));
        rmax1 = fmaxf(rmax1, __shfl_xor_sync(0xffffffffu, rmax1, 2));

        float mn0 = fmaxf(m0, rmax0), mn1 = fmaxf(m1, rmax1);
        float corr0 = __expf(m0 - mn0), corr1 = __expf(m1 - mn1);
        m0 = mn0; m1 = mn1;

        float ps0 = 0.f, ps1 = 0.f;
#pragma unroll
        for (int nt = 0; nt < 8; nt++) {
            sacc[nt][0] = __expf(sacc[nt][0] - m0);
            sacc[nt][1] = __expf(sacc[nt][1] - m0);
            sacc[nt][2] = __expf(sacc[nt][2] - m1);
            sacc[nt][3] = __expf(sacc[nt][3] - m1);
            ps0 += sacc[nt][0] + sacc[nt][1];
            ps1 += sacc[nt][2] + sacc[nt][3];
            o[nt][0] *= corr0; o[nt][1] *= corr0;
            o[nt][2] *= corr1; o[nt][3] *= corr1;
        }
        l0 = l0 * corr0 + ps0;
        l1 = l1 * corr1 + ps1;

        // ---- store P to smem (warp-private rows; reuse Q region) ----
#pragma unroll
        for (int nt = 0; nt < 8; nt++) {
            *(float2*)&QP[r0p * QPITCH + nt * 8 + 2 * tig] =
                make_float2(sacc[nt][0], sacc[nt][1]);
            *(float2*)&QP[(r0p + 8) * QPITCH + nt * 8 + 2 * tig] =
                make_float2(sacc[nt][2], sacc[nt][3]);
        }
        __syncwarp();

        // ---- O += P @ V ----
#pragma unroll
        for (int kt = 0; kt < 8; kt++) {
            uint32_t av[4];
            av[0] = f2tf(QP[r0p * QPITCH + kt * 8 + tig]);
            av[1] = f2tf(QP[(r0p + 8) * QPITCH + kt * 8 + tig]);
            av[2] = f2tf(QP[r0p * QPITCH + kt * 8 + tig + 4]);
            av[3] = f2tf(QP[(r0p + 8) * QPITCH + kt * 8 + tig + 4]);
#pragma unroll
            for (int nt = 0; nt < 8; nt++) {
                const float* vb = &Vs[vofs + (kt * 8 + tig) * VPITCH + nt * 8 + g];
                uint32_t b0 = f2tf(vb[0]);
                uint32_t b1 = f2tf(vb[4 * VPITCH]);
                mma_tf32(o[nt], av, b0, b1);
            }
        }
        // next iteration's leading __syncthreads orders P reads vs next store
    }

    // ---- normalize and write ----
    l0 += __shfl_xor_sync(0xffffffffu, l0, 1);
    l0 += __shfl_xor_sync(0xffffffffu, l0, 2);
    l1 += __shfl_xor_sync(0xffffffffu, l1, 1);
    l1 += __shfl_xor_sync(0xffffffffu, l1, 2);
    float inv0 = 1.0f / l0, inv1 = 1.0f / l1;

#pragma unroll
    for (int nt = 0; nt < 8; nt++) {
        int cc = nt * 8 + 2 * tig;
        *(float2*)&Ob[(size_t)qrow0 * D_ + cc] =
            make_float2(o[nt][0] * inv0, o[nt][1] * inv0);
        *(float2*)&Ob[(size_t)qrow1 * D_ + cc] =
            make_float2(o[nt][2] * inv1, o[nt][3] * inv1);
    }
}

// ---------------------------------------------------------------------------
extern "C" void kernel_launch(void* const* d_in, const int* in_sizes, int n_in,
                              void* d_out, int out_size)
{
    (void)in_sizes; (void)n_in; (void)out_size;
    const float* x  = (const float*)d_in[0];
    const float* Wq = (const float*)d_in[1];
    const float* Wk = (const float*)d_in[2];
    const float* Wv = (const float*)d_in[3];
    const float* Wo = (const float*)d_in[4];
    float* out = (float*)d_out;

    float *qp, *kp, *vp, *ap;
    cudaGetSymbolAddress((void**)&qp, g_Q);
    cudaGetSymbolAddress((void**)&kp, g_K);
    cudaGetSymbolAddress((void**)&vp, g_V);
    cudaGetSymbolAddress((void**)&ap, g_att);

    cudaFuncSetAttribute(gemm_tf32, cudaFuncAttributeMaxDynamicSharedMemorySize, GSMEM);
    cudaFuncSetAttribute(attn_tc,   cudaFuncAttributeMaxDynamicSharedMemorySize, ASMEM);

    dim3 gg(D_ / 128, MTOT / 128);   // (8, 32)
    gemm_tf32<<<gg, 256, GSMEM>>>(x, Wq, qp, MTOT, D_, D_);
    gemm_tf32<<<gg, 256, GSMEM>>>(x, Wk, kp, MTOT, D_, D_);
    gemm_tf32<<<gg, 256, GSMEM>>>(x, Wv, vp, MTOT, D_, D_);

    attn_tc<<<dim3(S_ / 128, B_ * H_), 256, ASMEM>>>(qp, kp, vp, ap);

    gemm_tf32<<<gg, 256, GSMEM>>>(ap, Wo, out, MTOT, D_, D_);
}

// round 7
// speedup vs baseline: 3.3815x; 1.0571x over previous
#include <cuda_runtime.h>
#include <cstdint>

#define B_   2
#define S_   2048
#define D_   1024
#define H_   16
#define DK_  64
#define MTOT (B_ * S_)   // 4096

// ---------------------------------------------------------------------------
// Scratch (device globals — no allocation allowed)
// ---------------------------------------------------------------------------
__device__ float g_Q[MTOT * D_];
__device__ float g_K[MTOT * D_];
__device__ float g_V[MTOT * D_];
__device__ float g_att[MTOT * D_];

// ---------------------------------------------------------------------------
// Helpers (baseline PTX only — no sm_103a-feature instructions)
// ---------------------------------------------------------------------------
__device__ __forceinline__ uint32_t smem_u32(const void* p) {
    uint32_t a;
    asm("{ .reg .u64 t; cvta.to.shared.u64 t, %1; cvt.u32.u64 %0, t; }"
        : "=r"(a) : "l"(p));
    return a;
}
__device__ __forceinline__ void cp16(uint32_t s, const void* g) {
    asm volatile("cp.async.cg.shared.global [%0], [%1], 16;"
                 :: "r"(s), "l"(g) : "memory");
}
#define CP_COMMIT() asm volatile("cp.async.commit_group;" ::: "memory")
#define CP_WAIT(n)  asm volatile("cp.async.wait_group %0;" :: "n"(n) : "memory")

__device__ __forceinline__ uint32_t f2tf(float f) {
    uint32_t u;
    asm("cvt.rna.tf32.f32 %0, %1;" : "=r"(u) : "f"(f));
    return u;
}
__device__ __forceinline__ void mma_tf32(float* c, const uint32_t* a,
                                         uint32_t b0, uint32_t b1) {
    asm volatile(
        "mma.sync.aligned.m16n8k8.row.col.f32.tf32.tf32.f32 "
        "{%0,%1,%2,%3}, {%4,%5,%6,%7}, {%8,%9}, {%0,%1,%2,%3};"
        : "+f"(c[0]), "+f"(c[1]), "+f"(c[2]), "+f"(c[3])
        : "r"(a[0]), "r"(a[1]), "r"(a[2]), "r"(a[3]), "r"(b0), "r"(b1));
}

// ---------------------------------------------------------------------------
// TF32 tensor-core GEMM core. C[M,N] = A[M,K] @ W[K,N]
// 128x128 CTA tile, 8 warps (2x4), K-chunks of 32, cp.async double buffer.
// __launch_bounds__(256,2): 2 CTAs/SM (regs<=128, 2x70KB smem fits).
// ---------------------------------------------------------------------------
#define KCH     32
#define APITCH  36
#define BPITCH  136
#define AFLOATS (128 * APITCH)
#define BFLOATS (KCH * BPITCH)
#define ABYTES  (AFLOATS * 4)
#define BBYTES  (BFLOATS * 4)
#define GSMEM   (2 * (ABYTES + BBYTES)) // 71680 B

__device__ __forceinline__ void gemm_body(const float* __restrict__ A,
                                          const float* __restrict__ W,
                                          float* __restrict__ C,
                                          int bx, int by, int N, int K,
                                          float* sm)
{
    const int tid  = threadIdx.x;
    const int wid  = tid >> 5;
    const int lane = tid & 31;
    const int g    = lane >> 2;
    const int tig  = lane & 3;
    const int m0w  = (wid >> 2) * 64;
    const int n0w  = (wid & 3) * 32;

    const float* Ab = A + (size_t)by * 128 * K;
    const float* Wb = W + bx * 128;
    const uint32_t sbase = smem_u32(sm);

    float acc[4][4][4];
#pragma unroll
    for (int i = 0; i < 4; i++)
#pragma unroll
        for (int j = 0; j < 4; j++)
#pragma unroll
            for (int q = 0; q < 4; q++) acc[i][j][q] = 0.f;

    const int NC = K / KCH;

    auto copy_chunk = [&](int c, int buf) {
        const float* Ac = Ab + c * KCH;
        const float* Bc = Wb + (size_t)c * KCH * N;
        uint32_t ab = sbase + (uint32_t)buf * ABYTES;
        uint32_t bb = sbase + 2u * ABYTES + (uint32_t)buf * BBYTES;
#pragma unroll
        for (int p = 0; p < 4; p++) {
            int idx = tid + p * 256;
            int r  = idx >> 3, kq = (idx & 7) << 2;
            cp16(ab + (uint32_t)(r * APITCH + kq) * 4, Ac + (size_t)r * K + kq);
            int kb = idx >> 5, nq = (idx & 31) << 2;
            cp16(bb + (uint32_t)(kb * BPITCH + nq) * 4, Bc + (size_t)kb * N + nq);
        }
        CP_COMMIT();
    };

    copy_chunk(0, 0);

    for (int c = 0; c < NC; c++) {
        const int buf = c & 1;
        if (c + 1 < NC) { copy_chunk(c + 1, buf ^ 1); CP_WAIT(1); }
        else            { CP_WAIT(0); }
        __syncthreads();

        const float* As = sm + buf * AFLOATS;
        const float* Bs = sm + 2 * AFLOATS + buf * BFLOATS;

#pragma unroll
        for (int kk = 0; kk < KCH; kk += 8) {
            uint32_t a[4][4];
#pragma unroll
            for (int i = 0; i < 4; i++) {
                int r = m0w + 16 * i + g;
                a[i][0] = f2tf(As[r * APITCH + kk + tig]);
                a[i][1] = f2tf(As[(r + 8) * APITCH + kk + tig]);
                a[i][2] = f2tf(As[r * APITCH + kk + tig + 4]);
                a[i][3] = f2tf(As[(r + 8) * APITCH + kk + tig + 4]);
            }
#pragma unroll
            for (int j = 0; j < 4; j++) {
                uint32_t b0 = f2tf(Bs[(kk + tig) * BPITCH + n0w + 8 * j + g]);
                uint32_t b1 = f2tf(Bs[(kk + tig + 4) * BPITCH + n0w + 8 * j + g]);
#pragma unroll
                for (int i = 0; i < 4; i++)
                    mma_tf32(acc[i][j], a[i], b0, b1);
            }
        }
        __syncthreads();
    }

#pragma unroll
    for (int i = 0; i < 4; i++) {
        int r0 = by * 128 + m0w + 16 * i + g;
#pragma unroll
        for (int j = 0; j < 4; j++) {
            int cc = bx * 128 + n0w + 8 * j + 2 * tig;
            *(float2*)&C[(size_t)r0 * N + cc] =
                make_float2(acc[i][j][0], acc[i][j][1]);
            *(float2*)&C[(size_t)(r0 + 8) * N + cc] =
                make_float2(acc[i][j][2], acc[i][j][3]);
        }
    }
}

// Fused Q/K/V projection: gridDim.x = 24; bx/8 selects weight+destination.
__global__ __launch_bounds__(256, 2) void gemm_qkv(const float* __restrict__ x,
                                                   const float* __restrict__ Wq,
                                                   const float* __restrict__ Wk,
                                                   const float* __restrict__ Wv,
                                                   float* __restrict__ Qo,
                                                   float* __restrict__ Ko,
                                                   float* __restrict__ Vo)
{
    extern __shared__ float sm[];
    const int sel = blockIdx.x >> 3;
    const int bx  = blockIdx.x & 7;
    const float* W = (sel == 0) ? Wq : (sel == 1) ? Wk : Wv;
    float*       C = (sel == 0) ? Qo : (sel == 1) ? Ko : Vo;
    gemm_body(x, W, C, bx, blockIdx.y, D_, D_, sm);
}

__global__ __launch_bounds__(256, 2) void gemm_tf32(const float* __restrict__ A,
                                                    const float* __restrict__ W,
                                                    float* __restrict__ C,
                                                    int M, int N, int K)
{
    extern __shared__ float sm[];
    gemm_body(A, W, C, blockIdx.x, blockIdx.y, N, K, sm);
}

// ---------------------------------------------------------------------------
// TF32 tensor-core causal flash attention (structure as R5).
// __launch_bounds__(256,2): 2 CTAs/SM (104KB smem x2 = 208KB <= 228KB,
// 128 regs x 512 thr = full RF).
// ---------------------------------------------------------------------------
#define QPITCH  68
#define VPITCH  72
#define OFF_K   8704
#define OFF_V   (8704 + 2 * 4352)
#define KBUF    4352                  // 64*68 floats
#define VBUF    4608                  // 64*72 floats
#define ASMEM   ((OFF_V + 2 * VBUF) * 4)   // 106496 B

__global__ __launch_bounds__(256, 2) void attn_tc(const float* __restrict__ Q,
                                                  const float* __restrict__ K,
                                                  const float* __restrict__ V,
                                                  float* __restrict__ O)
{
    extern __shared__ float sm[];
    float* QP = sm;                 // Q tile, later P tile
    float* Ks = sm + OFF_K;
    float* Vs = sm + OFF_V;

    const int tid  = threadIdx.x;
    const int wid  = tid >> 5;
    const int lane = tid & 31;
    const int g    = lane >> 2;
    const int tig  = lane & 3;

    const int qt = (int)gridDim.x - 1 - (int)blockIdx.x;   // heavy-first
    const int bh = blockIdx.y;
    const int b  = bh >> 4;
    const int h  = bh & 15;

    const size_t base = (size_t)b * S_ * D_ + (size_t)h * DK_;
    const float* Qb = Q + base;
    const float* Kb = K + base;
    const float* Vb = V + base;
    float*       Ob = O + base;

    const int q0  = qt * 128;
    const int r0p = wid * 16 + g;
    const uint32_t sb = smem_u32(sm);

    // ---- load Q tile (group 1) ----
#pragma unroll
    for (int p = 0; p < 8; p++) {
        int idx = tid + p * 256;
        int r = idx >> 4, c = (idx & 15) << 2;
        cp16(sb + (uint32_t)(r * QPITCH + c) * 4,
             Qb + (size_t)(q0 + r) * D_ + c);
    }
    CP_COMMIT();

    auto copy_kv = [&](int t, int buf) {
        const float* Kc = Kb + (size_t)(t * 64) * D_;
        const float* Vc = Vb + (size_t)(t * 64) * D_;
#pragma unroll
        for (int p = 0; p < 4; p++) {
            int idx = tid + p * 256;
            int r = idx >> 4, c = (idx & 15) << 2;
            cp16(sb + (uint32_t)(OFF_K + buf * KBUF + r * QPITCH + c) * 4,
                 Kc + (size_t)r * D_ + c);
            cp16(sb + (uint32_t)(OFF_V + buf * VBUF + r * VPITCH + c) * 4,
                 Vc + (size_t)r * D_ + c);
        }
        CP_COMMIT();
    };

    copy_kv(0, 0);      // group 2

    CP_WAIT(1);         // Q ready (kv0 may be in flight)
    __syncthreads();

    // ---- preload Q fragments (scaled by 1/sqrt(DK) = 1/8, exact) ----
    uint32_t qf[8][4];
#pragma unroll
    for (int kt = 0; kt < 8; kt++) {
        int kk = kt * 8;
        qf[kt][0] = f2tf(QP[r0p * QPITCH + kk + tig] * 0.125f);
        qf[kt][1] = f2tf(QP[(r0p + 8) * QPITCH + kk + tig] * 0.125f);
        qf[kt][2] = f2tf(QP[r0p * QPITCH + kk + tig + 4] * 0.125f);
        qf[kt][3] = f2tf(QP[(r0p + 8) * QPITCH + kk + tig + 4] * 0.125f);
    }
    __syncthreads();    // all warps read Q before P overwrites the region

    float m0 = -1e30f, m1 = -1e30f, l0 = 0.f, l1 = 0.f;
    float o[8][4];
#pragma unroll
    for (int nt = 0; nt < 8; nt++)
#pragma unroll
        for (int c = 0; c < 4; c++) o[nt][c] = 0.f;

    const int qrow0 = q0 + r0p;
    const int qrow1 = qrow0 + 8;
    const int ntiles = 2 * qt + 2;

    for (int t = 0; t < ntiles; t++) {
        const int buf = t & 1;
        CP_WAIT(0);
        __syncthreads();            // tile t ready; all warps done with t-1
        if (t + 1 < ntiles) copy_kv(t + 1, buf ^ 1);

        const int kofs = buf * KBUF;
        const int vofs = buf * VBUF;
        const int kv0  = t * 64;

        // ---- scores S = Q @ K^T ----
        float sacc[8][4];
#pragma unroll
        for (int nt = 0; nt < 8; nt++)
#pragma unroll
            for (int c = 0; c < 4; c++) sacc[nt][c] = 0.f;

#pragma unroll
        for (int kt = 0; kt < 8; kt++) {
#pragma unroll
            for (int nt = 0; nt < 8; nt++) {
                const float* kb = &Ks[kofs + (nt * 8 + g) * QPITCH + kt * 8 + tig];
                uint32_t b0 = f2tf(kb[0]);
                uint32_t b1 = f2tf(kb[4]);
                mma_tf32(sacc[nt], qf[kt], b0, b1);
            }
        }

        // ---- causal mask (only tiles intersecting the diagonal) ----
        if (kv0 + 63 > q0) {
#pragma unroll
            for (int nt = 0; nt < 8; nt++) {
                int c0 = kv0 + nt * 8 + 2 * tig;
                if (c0     > qrow0) sacc[nt][0] = -1e30f;
                if (c0 + 1 > qrow0) sacc[nt][1] = -1e30f;
                if (c0     > qrow1) sacc[nt][2] = -1e30f;
                if (c0 + 1 > qrow1) sacc[nt][3] = -1e30f;
            }
        }

        // ---- online softmax (rows live on 4-lane groups) ----
        float rmax0 = -1e30f, rmax1 = -1e30f;
#pragma unroll
        for (int nt = 0; nt < 8; nt++) {
            rmax0 = fmaxf(rmax0, fmaxf(sacc[nt][0], sacc[nt][1]));
            rmax1 = fmaxf(rmax1, fmaxf(sacc[nt][2], sacc[nt][3]));
        }
        rmax0 = fmaxf(rmax0, __shfl_xor_sync(0xffffffffu, rmax0, 1));
        rmax0 = fmaxf(rmax0, __shfl_xor_sync(0xffffffffu, rmax0, 2));
        rmax1 = fmaxf(rmax1, __shfl_xor_sync(0xffffffffu, rmax1, 1));
        rmax1 = fmaxf(rmax1, __shfl_xor_sync(0xffffffffu, rmax1, 2));

        float mn0 = fmaxf(m0, rmax0), mn1 = fmaxf(m1, rmax1);
        float corr0 = __expf(m0 - mn0), corr1 = __expf(m1 - mn1);
        m0 = mn0; m1 = mn1;

        float ps0 = 0.f, ps1 = 0.f;
#pragma unroll
        for (int nt = 0; nt < 8; nt++) {
            sacc[nt][0] = __expf(sacc[nt][0] - m0);
            sacc[nt][1] = __expf(sacc[nt][1] - m0);
            sacc[nt][2] = __expf(sacc[nt][2] - m1);
            sacc[nt][3] = __expf(sacc[nt][3] - m1);
            ps0 += sacc[nt][0] + sacc[nt][1];
            ps1 += sacc[nt][2] + sacc[nt][3];
            o[nt][0] *= corr0; o[nt][1] *= corr0;
            o[nt][2] *= corr1; o[nt][3] *= corr1;
        }
        l0 = l0 * corr0 + ps0;
        l1 = l1 * corr1 + ps1;

        // ---- store P to smem (warp-private rows; reuse Q region) ----
#pragma unroll
        for (int nt = 0; nt < 8; nt++) {
            *(float2*)&QP[r0p * QPITCH + nt * 8 + 2 * tig] =
                make_float2(sacc[nt][0], sacc[nt][1]);
            *(float2*)&QP[(r0p + 8) * QPITCH + nt * 8 + 2 * tig] =
                make_float2(sacc[nt][2], sacc[nt][3]);
        }
        __syncwarp();

        // ---- O += P @ V ----
#pragma unroll
        for (int kt = 0; kt < 8; kt++) {
            uint32_t av[4];
            av[0] = f2tf(QP[r0p * QPITCH + kt * 8 + tig]);
            av[1] = f2tf(QP[(r0p + 8) * QPITCH + kt * 8 + tig]);
            av[2] = f2tf(QP[r0p * QPITCH + kt * 8 + tig + 4]);
            av[3] = f2tf(QP[(r0p + 8) * QPITCH + kt * 8 + tig + 4]);
#pragma unroll
            for (int nt = 0; nt < 8; nt++) {
                const float* vb = &Vs[vofs + (kt * 8 + tig) * VPITCH + nt * 8 + g];
                uint32_t b0 = f2tf(vb[0]);
                uint32_t b1 = f2tf(vb[4 * VPITCH]);
                mma_tf32(o[nt], av, b0, b1);
            }
        }
        // next iteration's leading __syncthreads orders P reads vs next store
    }

    // ---- normalize and write ----
    l0 += __shfl_xor_sync(0xffffffffu, l0, 1);
    l0 += __shfl_xor_sync(0xffffffffu, l0, 2);
    l1 += __shfl_xor_sync(0xffffffffu, l1, 1);
    l1 += __shfl_xor_sync(0xffffffffu, l1, 2);
    float inv0 = 1.0f / l0, inv1 = 1.0f / l1;

#pragma unroll
    for (int nt = 0; nt < 8; nt++) {
        int cc = nt * 8 + 2 * tig;
        *(float2*)&Ob[(size_t)qrow0 * D_ + cc] =
            make_float2(o[nt][0] * inv0, o[nt][1] * inv0);
        *(float2*)&Ob[(size_t)qrow1 * D_ + cc] =
            make_float2(o[nt][2] * inv1, o[nt][3] * inv1);
    }
}

// ---------------------------------------------------------------------------
extern "C" void kernel_launch(void* const* d_in, const int* in_sizes, int n_in,
                              void* d_out, int out_size)
{
    (void)in_sizes; (void)n_in; (void)out_size;
    const float* x  = (const float*)d_in[0];
    const float* Wq = (const float*)d_in[1];
    const float* Wk = (const float*)d_in[2];
    const float* Wv = (const float*)d_in[3];
    const float* Wo = (const float*)d_in[4];
    float* out = (float*)d_out;

    float *qp, *kp, *vp, *ap;
    cudaGetSymbolAddress((void**)&qp, g_Q);
    cudaGetSymbolAddress((void**)&kp, g_K);
    cudaGetSymbolAddress((void**)&vp, g_V);
    cudaGetSymbolAddress((void**)&ap, g_att);

    cudaFuncSetAttribute(gemm_qkv,  cudaFuncAttributeMaxDynamicSharedMemorySize, GSMEM);
    cudaFuncSetAttribute(gemm_tf32, cudaFuncAttributeMaxDynamicSharedMemorySize, GSMEM);
    cudaFuncSetAttribute(attn_tc,   cudaFuncAttributeMaxDynamicSharedMemorySize, ASMEM);

    gemm_qkv<<<dim3(24, MTOT / 128), 256, GSMEM>>>(x, Wq, Wk, Wv, qp, kp, vp);

    attn_tc<<<dim3(S_ / 128, B_ * H_), 256, ASMEM>>>(qp, kp, vp, ap);

    gemm_tf32<<<dim3(D_ / 128, MTOT / 128), 256, GSMEM>>>(ap, Wo, out, MTOT, D_, D_);
}

// round 8
// speedup vs baseline: 3.7452x; 1.1076x over previous
#include <cuda_runtime.h>
#include <cstdint>

#define B_   2
#define S_   2048
#define D_   1024
#define H_   16
#define DK_  64
#define MTOT (B_ * S_)   // 4096

// ---------------------------------------------------------------------------
// Scratch (device globals — no allocation allowed)
// ---------------------------------------------------------------------------
__device__ float g_Q[MTOT * D_];
__device__ float g_K[MTOT * D_];
__device__ float g_V[MTOT * D_];
__device__ float g_att[MTOT * D_];
__device__ float g_xr[MTOT * D_];        // x, tf32-pre-rounded
__device__ float g_wr[4 * D_ * D_];      // Wq,Wk,Wv,Wo, tf32-pre-rounded

// ---------------------------------------------------------------------------
// Helpers (baseline PTX only)
// ---------------------------------------------------------------------------
__device__ __forceinline__ uint32_t smem_u32(const void* p) {
    uint32_t a;
    asm("{ .reg .u64 t; cvta.to.shared.u64 t, %1; cvt.u32.u64 %0, t; }"
        : "=r"(a) : "l"(p));
    return a;
}
__device__ __forceinline__ void cp16(uint32_t s, const void* g) {
    asm volatile("cp.async.cg.shared.global [%0], [%1], 16;"
                 :: "r"(s), "l"(g) : "memory");
}
#define CP_COMMIT() asm volatile("cp.async.commit_group;" ::: "memory")
#define CP_WAIT(n)  asm volatile("cp.async.wait_group %0;" :: "n"(n) : "memory")

__device__ __forceinline__ uint32_t f2tf(float f) {
    uint32_t u;
    asm("cvt.rna.tf32.f32 %0, %1;" : "=r"(u) : "f"(f));
    return u;
}
__device__ __forceinline__ float rtf(float f) {      // round to tf32-representable fp32
    return __uint_as_float(f2tf(f));
}
__device__ __forceinline__ void mma_tf32(float* c, const uint32_t* a,
                                         uint32_t b0, uint32_t b1) {
    asm volatile(
        "mma.sync.aligned.m16n8k8.row.col.f32.tf32.tf32.f32 "
        "{%0,%1,%2,%3}, {%4,%5,%6,%7}, {%8,%9}, {%0,%1,%2,%3};"
        : "+f"(c[0]), "+f"(c[1]), "+f"(c[2]), "+f"(c[3])
        : "r"(a[0]), "r"(a[1]), "r"(a[2]), "r"(a[3]), "r"(b0), "r"(b1));
}

// ---------------------------------------------------------------------------
// Prep: round fp32 -> tf32-representable fp32 (rna), elementwise.
// ---------------------------------------------------------------------------
__global__ __launch_bounds__(256) void round_x(const float* __restrict__ in,
                                               float* __restrict__ out)
{
    int i = blockIdx.x * 256 + threadIdx.x;
    float4 v = ((const float4*)in)[i];
    ((float4*)out)[i] = make_float4(rtf(v.x), rtf(v.y), rtf(v.z), rtf(v.w));
}

__global__ __launch_bounds__(256) void round_w4(const float* __restrict__ w0,
                                                const float* __restrict__ w1,
                                                const float* __restrict__ w2,
                                                const float* __restrict__ w3,
                                                float* __restrict__ dst)
{
    const int by = blockIdx.y;
    const float* src = (by == 0) ? w0 : (by == 1) ? w1 : (by == 2) ? w2 : w3;
    int i = blockIdx.x * 256 + threadIdx.x;
    float4 v = ((const float4*)src)[i];
    ((float4*)(dst + (size_t)by * D_ * D_))[i] =
        make_float4(rtf(v.x), rtf(v.y), rtf(v.z), rtf(v.w));
}

// ---------------------------------------------------------------------------
// TF32 tensor-core GEMM core. Inputs MUST be tf32-pre-rounded: fragment loads
// are plain LDS (bits pass through mma unchanged). ROUND: round outputs.
// ---------------------------------------------------------------------------
#define KCH     32
#define APITCH  36
#define BPITCH  136
#define AFLOATS (128 * APITCH)
#define BFLOATS (KCH * BPITCH)
#define ABYTES  (AFLOATS * 4)
#define BBYTES  (BFLOATS * 4)
#define GSMEM   (2 * (ABYTES + BBYTES)) // 71680 B

template <int ROUND>
__device__ __forceinline__ void gemm_body(const float* __restrict__ A,
                                          const float* __restrict__ W,
                                          float* __restrict__ C,
                                          int bx, int by, int N, int K,
                                          float* sm)
{
    const int tid  = threadIdx.x;
    const int wid  = tid >> 5;
    const int lane = tid & 31;
    const int g    = lane >> 2;
    const int tig  = lane & 3;
    const int m0w  = (wid >> 2) * 64;
    const int n0w  = (wid & 3) * 32;

    const float* Ab = A + (size_t)by * 128 * K;
    const float* Wb = W + bx * 128;
    const uint32_t sbase = smem_u32(sm);

    float acc[4][4][4];
#pragma unroll
    for (int i = 0; i < 4; i++)
#pragma unroll
        for (int j = 0; j < 4; j++)
#pragma unroll
            for (int q = 0; q < 4; q++) acc[i][j][q] = 0.f;

    const int NC = K / KCH;

    auto copy_chunk = [&](int c, int buf) {
        const float* Ac = Ab + c * KCH;
        const float* Bc = Wb + (size_t)c * KCH * N;
        uint32_t ab = sbase + (uint32_t)buf * ABYTES;
        uint32_t bb = sbase + 2u * ABYTES + (uint32_t)buf * BBYTES;
#pragma unroll
        for (int p = 0; p < 4; p++) {
            int idx = tid + p * 256;
            int r  = idx >> 3, kq = (idx & 7) << 2;
            cp16(ab + (uint32_t)(r * APITCH + kq) * 4, Ac + (size_t)r * K + kq);
            int kb = idx >> 5, nq = (idx & 31) << 2;
            cp16(bb + (uint32_t)(kb * BPITCH + nq) * 4, Bc + (size_t)kb * N + nq);
        }
        CP_COMMIT();
    };

    copy_chunk(0, 0);

    for (int c = 0; c < NC; c++) {
        const int buf = c & 1;
        if (c + 1 < NC) { copy_chunk(c + 1, buf ^ 1); CP_WAIT(1); }
        else            { CP_WAIT(0); }
        __syncthreads();

        const float* As = sm + buf * AFLOATS;
        const float* Bs = sm + 2 * AFLOATS + buf * BFLOATS;

#pragma unroll
        for (int kk = 0; kk < KCH; kk += 8) {
            uint32_t a[4][4];
#pragma unroll
            for (int i = 0; i < 4; i++) {
                int r = m0w + 16 * i + g;
                a[i][0] = __float_as_uint(As[r * APITCH + kk + tig]);
                a[i][1] = __float_as_uint(As[(r + 8) * APITCH + kk + tig]);
                a[i][2] = __float_as_uint(As[r * APITCH + kk + tig + 4]);
                a[i][3] = __float_as_uint(As[(r + 8) * APITCH + kk + tig + 4]);
            }
#pragma unroll
            for (int j = 0; j < 4; j++) {
                uint32_t b0 = __float_as_uint(Bs[(kk + tig) * BPITCH + n0w + 8 * j + g]);
                uint32_t b1 = __float_as_uint(Bs[(kk + tig + 4) * BPITCH + n0w + 8 * j + g]);
#pragma unroll
                for (int i = 0; i < 4; i++)
                    mma_tf32(acc[i][j], a[i], b0, b1);
            }
        }
        __syncthreads();
    }

#pragma unroll
    for (int i = 0; i < 4; i++) {
        int r0 = by * 128 + m0w + 16 * i + g;
#pragma unroll
        for (int j = 0; j < 4; j++) {
            int cc = bx * 128 + n0w + 8 * j + 2 * tig;
            if (ROUND) {
                *(float2*)&C[(size_t)r0 * N + cc] =
                    make_float2(rtf(acc[i][j][0]), rtf(acc[i][j][1]));
                *(float2*)&C[(size_t)(r0 + 8) * N + cc] =
                    make_float2(rtf(acc[i][j][2]), rtf(acc[i][j][3]));
            } else {
                *(float2*)&C[(size_t)r0 * N + cc] =
                    make_float2(acc[i][j][0], acc[i][j][1]);
                *(float2*)&C[(size_t)(r0 + 8) * N + cc] =
                    make_float2(acc[i][j][2], acc[i][j][3]);
            }
        }
    }
}

// Fused Q/K/V projection: gridDim.x = 24; bx/8 selects weight+destination.
// Outputs tf32-pre-rounded (consumed by attention fragments).
__global__ __launch_bounds__(256, 2) void gemm_qkv(const float* __restrict__ x,
                                                   const float* __restrict__ Wr,
                                                   float* __restrict__ Qo,
                                                   float* __restrict__ Ko,
                                                   float* __restrict__ Vo)
{
    extern __shared__ float sm[];
    const int sel = blockIdx.x >> 3;
    const int bx  = blockIdx.x & 7;
    const float* W = Wr + (size_t)sel * D_ * D_;
    float*       C = (sel == 0) ? Qo : (sel == 1) ? Ko : Vo;
    gemm_body<1>(x, W, C, bx, blockIdx.y, D_, D_, sm);
}

// Output projection: full fp32 output (no rounding).
__global__ __launch_bounds__(256, 2) void gemm_out(const float* __restrict__ A,
                                                   const float* __restrict__ W,
                                                   float* __restrict__ C)
{
    extern __shared__ float sm[];
    gemm_body<0>(A, W, C, blockIdx.x, blockIdx.y, D_, D_, sm);
}

// ---------------------------------------------------------------------------
// TF32 tensor-core causal flash attention. Q/K/V tf32-pre-rounded by gemm_qkv
// -> all fragment loads are plain LDS. P rounded once at STS. Output rounded
// (consumed by gemm_out fragments).
// ---------------------------------------------------------------------------
#define QPITCH  68
#define VPITCH  72
#define OFF_K   8704
#define OFF_V   (8704 + 2 * 4352)
#define KBUF    4352                  // 64*68 floats
#define VBUF    4608                  // 64*72 floats
#define ASMEM   ((OFF_V + 2 * VBUF) * 4)   // 106496 B

__global__ __launch_bounds__(256, 2) void attn_tc(const float* __restrict__ Q,
                                                  const float* __restrict__ K,
                                                  const float* __restrict__ V,
                                                  float* __restrict__ O)
{
    extern __shared__ float sm[];
    float* QP = sm;                 // Q tile, later P tile
    float* Ks = sm + OFF_K;
    float* Vs = sm + OFF_V;

    const int tid  = threadIdx.x;
    const int wid  = tid >> 5;
    const int lane = tid & 31;
    const int g    = lane >> 2;
    const int tig  = lane & 3;

    const int qt = (int)gridDim.x - 1 - (int)blockIdx.x;   // heavy-first
    const int bh = blockIdx.y;
    const int b  = bh >> 4;
    const int h  = bh & 15;

    const size_t base = (size_t)b * S_ * D_ + (size_t)h * DK_;
    const float* Qb = Q + base;
    const float* Kb = K + base;
    const float* Vb = V + base;
    float*       Ob = O + base;

    const int q0  = qt * 128;
    const int r0p = wid * 16 + g;
    const uint32_t sb = smem_u32(sm);

    // ---- load Q tile (group 1) ----
#pragma unroll
    for (int p = 0; p < 8; p++) {
        int idx = tid + p * 256;
        int r = idx >> 4, c = (idx & 15) << 2;
        cp16(sb + (uint32_t)(r * QPITCH + c) * 4,
             Qb + (size_t)(q0 + r) * D_ + c);
    }
    CP_COMMIT();

    auto copy_kv = [&](int t, int buf) {
        const float* Kc = Kb + (size_t)(t * 64) * D_;
        const float* Vc = Vb + (size_t)(t * 64) * D_;
#pragma unroll
        for (int p = 0; p < 4; p++) {
            int idx = tid + p * 256;
            int r = idx >> 4, c = (idx & 15) << 2;
            cp16(sb + (uint32_t)(OFF_K + buf * KBUF + r * QPITCH + c) * 4,
                 Kc + (size_t)r * D_ + c);
            cp16(sb + (uint32_t)(OFF_V + buf * VBUF + r * VPITCH + c) * 4,
                 Vc + (size_t)r * D_ + c);
        }
        CP_COMMIT();
    };

    copy_kv(0, 0);      // group 2

    CP_WAIT(1);         // Q ready (kv0 may be in flight)
    __syncthreads();

    // ---- preload Q fragments (x 1/8 = exponent shift, stays tf32-exact) ----
    uint32_t qf[8][4];
#pragma unroll
    for (int kt = 0; kt < 8; kt++) {
        int kk = kt * 8;
        qf[kt][0] = __float_as_uint(QP[r0p * QPITCH + kk + tig] * 0.125f);
        qf[kt][1] = __float_as_uint(QP[(r0p + 8) * QPITCH + kk + tig] * 0.125f);
        qf[kt][2] = __float_as_uint(QP[r0p * QPITCH + kk + tig + 4] * 0.125f);
        qf[kt][3] = __float_as_uint(QP[(r0p + 8) * QPITCH + kk + tig + 4] * 0.125f);
    }
    __syncthreads();    // all warps read Q before P overwrites the region

    float m0 = -1e30f, m1 = -1e30f, l0 = 0.f, l1 = 0.f;
    float o[8][4];
#pragma unroll
    for (int nt = 0; nt < 8; nt++)
#pragma unroll
        for (int c = 0; c < 4; c++) o[nt][c] = 0.f;

    const int qrow0 = q0 + r0p;
    const int qrow1 = qrow0 + 8;
    const int ntiles = 2 * qt + 2;

    for (int t = 0; t < ntiles; t++) {
        const int buf = t & 1;
        CP_WAIT(0);
        __syncthreads();            // tile t ready; all warps done with t-1
        if (t + 1 < ntiles) copy_kv(t + 1, buf ^ 1);

        const int kofs = buf * KBUF;
        const int vofs = buf * VBUF;
        const int kv0  = t * 64;

        // ---- scores S = Q @ K^T ----
        float sacc[8][4];
#pragma unroll
        for (int nt = 0; nt < 8; nt++)
#pragma unroll
            for (int c = 0; c < 4; c++) sacc[nt][c] = 0.f;

#pragma unroll
        for (int kt = 0; kt < 8; kt++) {
#pragma unroll
            for (int nt = 0; nt < 8; nt++) {
                const float* kb = &Ks[kofs + (nt * 8 + g) * QPITCH + kt * 8 + tig];
                uint32_t b0 = __float_as_uint(kb[0]);
                uint32_t b1 = __float_as_uint(kb[4]);
                mma_tf32(sacc[nt], qf[kt], b0, b1);
            }
        }

        // ---- causal mask (only tiles intersecting the diagonal) ----
        if (kv0 + 63 > q0) {
#pragma unroll
            for (int nt = 0; nt < 8; nt++) {
                int c0 = kv0 + nt * 8 + 2 * tig;
                if (c0     > qrow0) sacc[nt][0] = -1e30f;
                if (c0 + 1 > qrow0) sacc[nt][1] = -1e30f;
                if (c0     > qrow1) sacc[nt][2] = -1e30f;
                if (c0 + 1 > qrow1) sacc[nt][3] = -1e30f;
            }
        }

        // ---- online softmax (rows live on 4-lane groups) ----
        float rmax0 = -1e30f, rmax1 = -1e30f;
#pragma unroll
        for (int nt = 0; nt < 8; nt++) {
            rmax0 = fmaxf(rmax0, fmaxf(sacc[nt][0], sacc[nt][1]));
            rmax1 = fmaxf(rmax1, fmaxf(sacc[nt][2], sacc[nt][3]));
        }
        rmax0 = fmaxf(rmax0, __shfl_xor_sync(0xffffffffu, rmax0, 1));
        rmax0 = fmaxf(rmax0, __shfl_xor_sync(0xffffffffu, rmax0, 2));
        rmax1 = fmaxf(rmax1, __shfl_xor_sync(0xffffffffu, rmax1, 1));
        rmax1 = fmaxf(rmax1, __shfl_xor_sync(0xffffffffu, rmax1, 2));

        float mn0 = fmaxf(m0, rmax0), mn1 = fmaxf(m1, rmax1);
        float corr0 = __expf(m0 - mn0), corr1 = __expf(m1 - mn1);
        m0 = mn0; m1 = mn1;

        float ps0 = 0.f, ps1 = 0.f;
#pragma unroll
        for (int nt = 0; nt < 8; nt++) {
            sacc[nt][0] = __expf(sacc[nt][0] - m0);
            sacc[nt][1] = __expf(sacc[nt][1] - m0);
            sacc[nt][2] = __expf(sacc[nt][2] - m1);
            sacc[nt][3] = __expf(sacc[nt][3] - m1);
            ps0 += sacc[nt][0] + sacc[nt][1];
            ps1 += sacc[nt][2] + sacc[nt][3];
            o[nt][0] *= corr0; o[nt][1] *= corr0;
            o[nt][2] *= corr1; o[nt][3] *= corr1;
        }
        l0 = l0 * corr0 + ps0;
        l1 = l1 * corr1 + ps1;

        // ---- store P to smem, tf32-rounded (warp-private rows) ----
#pragma unroll
        for (int nt = 0; nt < 8; nt++) {
            *(float2*)&QP[r0p * QPITCH + nt * 8 + 2 * tig] =
                make_float2(rtf(sacc[nt][0]), rtf(sacc[nt][1]));
            *(float2*)&QP[(r0p + 8) * QPITCH + nt * 8 + 2 * tig] =
                make_float2(rtf(sacc[nt][2]), rtf(sacc[nt][3]));
        }
        __syncwarp();

        // ---- O += P @ V ----
#pragma unroll
        for (int kt = 0; kt < 8; kt++) {
            uint32_t av[4];
            av[0] = __float_as_uint(QP[r0p * QPITCH + kt * 8 + tig]);
            av[1] = __float_as_uint(QP[(r0p + 8) * QPITCH + kt * 8 + tig]);
            av[2] = __float_as_uint(QP[r0p * QPITCH + kt * 8 + tig + 4]);
            av[3] = __float_as_uint(QP[(r0p + 8) * QPITCH + kt * 8 + tig + 4]);
#pragma unroll
            for (int nt = 0; nt < 8; nt++) {
                const float* vb = &Vs[vofs + (kt * 8 + tig) * VPITCH + nt * 8 + g];
                uint32_t b0 = __float_as_uint(vb[0]);
                uint32_t b1 = __float_as_uint(vb[4 * VPITCH]);
                mma_tf32(o[nt], av, b0, b1);
            }
        }
        // next iteration's leading __syncthreads orders P reads vs next store
    }

    // ---- normalize and write (tf32-rounded for gemm_out) ----
    l0 += __shfl_xor_sync(0xffffffffu, l0, 1);
    l0 += __shfl_xor_sync(0xffffffffu, l0, 2);
    l1 += __shfl_xor_sync(0xffffffffu, l1, 1);
    l1 += __shfl_xor_sync(0xffffffffu, l1, 2);
    float inv0 = 1.0f / l0, inv1 = 1.0f / l1;

#pragma unroll
    for (int nt = 0; nt < 8; nt++) {
        int cc = nt * 8 + 2 * tig;
        *(float2*)&Ob[(size_t)qrow0 * D_ + cc] =
            make_float2(rtf(o[nt][0] * inv0), rtf(o[nt][1] * inv0));
        *(float2*)&Ob[(size_t)qrow1 * D_ + cc] =
            make_float2(rtf(o[nt][2] * inv1), rtf(o[nt][3] * inv1));
    }
}

// ---------------------------------------------------------------------------
extern "C" void kernel_launch(void* const* d_in, const int* in_sizes, int n_in,
                              void* d_out, int out_size)
{
    (void)in_sizes; (void)n_in; (void)out_size;
    const float* x  = (const float*)d_in[0];
    const float* Wq = (const float*)d_in[1];
    const float* Wk = (const float*)d_in[2];
    const float* Wv = (const float*)d_in[3];
    const float* Wo = (const float*)d_in[4];
    float* out = (float*)d_out;

    float *qp, *kp, *vp, *ap, *xr, *wr;
    cudaGetSymbolAddress((void**)&qp, g_Q);
    cudaGetSymbolAddress((void**)&kp, g_K);
    cudaGetSymbolAddress((void**)&vp, g_V);
    cudaGetSymbolAddress((void**)&ap, g_att);
    cudaGetSymbolAddress((void**)&xr, g_xr);
    cudaGetSymbolAddress((void**)&wr, g_wr);

    cudaFuncSetAttribute(gemm_qkv, cudaFuncAttributeMaxDynamicSharedMemorySize, GSMEM);
    cudaFuncSetAttribute(gemm_out, cudaFuncAttributeMaxDynamicSharedMemorySize, GSMEM);
    cudaFuncSetAttribute(attn_tc,  cudaFuncAttributeMaxDynamicSharedMemorySize, ASMEM);

    // Pre-round all GEMM operands to tf32-representable fp32
    round_x<<<(MTOT * D_) / (256 * 4), 256>>>(x, xr);
    round_w4<<<dim3((D_ * D_) / (256 * 4), 4), 256>>>(Wq, Wk, Wv, Wo, wr);

    gemm_qkv<<<dim3(24, MTOT / 128), 256, GSMEM>>>(xr, wr, qp, kp, vp);

    attn_tc<<<dim3(S_ / 128, B_ * H_), 256, ASMEM>>>(qp, kp, vp, ap);

    gemm_out<<<dim3(D_ / 128, MTOT / 128), 256, GSMEM>>>(ap, wr + 3 * (size_t)D_ * D_, out);
}